// round 14
// baseline (speedup 1.0000x reference)
#include <cuda_runtime.h>

#define NN 50000
#define NE 800000
#define D  64
#define NL 3
#define DCAT (D + NL * D)   // 256

typedef unsigned long long ull;

// ---------------- scratch (device globals; zero-initialized at load) --------
__device__ int   g_cnt1[NN], g_cnt2[NN], g_cur1[NN], g_cur2[NN];
__device__ int   g_off1[NN + 1], g_off2[NN + 1];
__device__ int   g_nbr1[NE], g_nbr2[NE];
__device__ __align__(16) float g_h[NN * D];
__device__ __align__(16) float g_s1[NN * D];
__device__ __align__(16) float g_s2[NN * D];
__device__ __align__(16) float g_cat[NN * DCAT];
__device__ __align__(16) float g_dump[NN * D];   // probe-only sink

__device__ __forceinline__ int clampi(int v) {
    return v < 0 ? 0 : (v >= NN ? NN - 1 : v);
}

// ---------------- packed f32x2 helpers ---------------------------------------
__device__ __forceinline__ void ffma2(ull& a, ull x, ull w) {
    asm("fma.rn.f32x2 %0, %1, %2, %0;" : "+l"(a) : "l"(x), "l"(w));
}
__device__ __forceinline__ float2 unpack2(ull v) {
    float2 r; asm("mov.b64 {%0,%1}, %2;" : "=f"(r.x), "=f"(r.y) : "l"(v)); return r;
}
__device__ __forceinline__ ull pack2(float x, float y) {
    ull r; asm("mov.b64 %0, {%1,%2};" : "=l"(r) : "f"(x), "f"(y)); return r;
}

// ---- init + edge histogram (cnt zeroed by previous call's k_fill) ----------
__global__ void k_init(const float* __restrict__ x, const int* __restrict__ ei) {
    int i = blockIdx.x * blockDim.x + threadIdx.x;
    if (i < NN * D) {
        float v = x[i];
        g_h[i] = v;
        g_cat[(i >> 6) * DCAT + (i & 63)] = v;
    }
    if (i < NE) {
        atomicAdd(&g_cnt1[clampi(ei[NE + i])], 1);
        atomicAdd(&g_cnt2[clampi(ei[i])], 1);
    }
}

// ---- exclusive scan (also re-zeroes g_cur) ----------------------------------
__global__ void k_scan() {
    __shared__ int ssum1[1024], ssum2[1024];
    const int t  = threadIdx.x;
    for (int i = t; i < NN; i += 1024) { g_cur1[i] = 0; g_cur2[i] = 0; }

    const int CH = (NN + 1023) / 1024;
    const int base = t * CH;
    int s1 = 0, s2 = 0;
    for (int i = 0; i < CH; i++) {
        int n = base + i;
        if (n < NN) { s1 += g_cnt1[n]; s2 += g_cnt2[n]; }
    }
    ssum1[t] = s1; ssum2[t] = s2;
    __syncthreads();

    for (int off = 1; off < 1024; off <<= 1) {
        int a1 = ssum1[t], a2 = ssum2[t];
        int b1 = (t >= off) ? ssum1[t - off] : 0;
        int b2 = (t >= off) ? ssum2[t - off] : 0;
        __syncthreads();
        ssum1[t] = a1 + b1; ssum2[t] = a2 + b2;
        __syncthreads();
    }

    int ex1 = (t == 0) ? 0 : ssum1[t - 1];
    int ex2 = (t == 0) ? 0 : ssum2[t - 1];
    for (int i = 0; i < CH; i++) {
        int n = base + i;
        if (n < NN) {
            g_off1[n] = ex1; ex1 += g_cnt1[n];
            g_off2[n] = ex2; ex2 += g_cnt2[n];
        }
    }
    if (t == 0) {
        g_off1[NN] = ssum1[1023];
        g_off2[NN] = ssum2[1023];
    }
}

// ---- fill edge lists (also re-zeroes g_cnt for next call) -------------------
__global__ void k_fill(const int* __restrict__ ei) {
    int e = blockIdx.x * blockDim.x + threadIdx.x;
    if (e >= NE) return;
    if (e < NN) { g_cnt1[e] = 0; g_cnt2[e] = 0; }
    int s = clampi(ei[e]);
    int d = clampi(ei[NE + e]);
    g_nbr1[g_off1[d] + atomicAdd(&g_cur1[d], 1)] = s;
    g_nbr2[g_off2[s] + atomicAdd(&g_cur2[s], 1)] = d;
}

// ======= agg v5 fused (R12 measured-best, 39.4us) ============================
__device__ __forceinline__ float4 gather_dir3(const int* __restrict__ nbr,
                                              const float4* __restrict__ hv,
                                              int b, int e, int half, int l16) {
    float4 a0 = make_float4(0.f, 0.f, 0.f, 0.f);
    float4 a1 = make_float4(0.f, 0.f, 0.f, 0.f);
    int j = b;
    for (; j + 8 <= e; j += 8) {                 // 8 nbrs: 4 idx + 4 LDG.128
        int i0 = __ldg(nbr + j     + half);
        int i1 = __ldg(nbr + j + 2 + half);
        int i2 = __ldg(nbr + j + 4 + half);
        int i3 = __ldg(nbr + j + 6 + half);
        float4 v0 = hv[i0 * 16 + l16];
        float4 v1 = hv[i1 * 16 + l16];
        float4 v2 = hv[i2 * 16 + l16];
        float4 v3 = hv[i3 * 16 + l16];
        a0.x += v0.x + v1.x; a0.y += v0.y + v1.y;
        a0.z += v0.z + v1.z; a0.w += v0.w + v1.w;
        a1.x += v2.x + v3.x; a1.y += v2.y + v3.y;
        a1.z += v2.z + v3.z; a1.w += v2.w + v3.w;
    }
    for (; j < e; j += 2) {
        int jj = j + half;
        if (jj < e) {
            int i0 = __ldg(nbr + jj);
            float4 v0 = hv[i0 * 16 + l16];
            a0.x += v0.x; a0.y += v0.y; a0.z += v0.z; a0.w += v0.w;
        }
    }
    a0.x += a1.x; a0.y += a1.y; a0.z += a1.z; a0.w += a1.w;
    return a0;
}

__global__ void k_agg() {
    int gw   = (blockIdx.x * blockDim.x + threadIdx.x) >> 5;
    int lane = threadIdx.x & 31;
    if (gw >= NN) return;
    const int n    = gw;
    const int half = lane >> 4;
    const int l16  = lane & 15;
    const float4* __restrict__ hv = (const float4*)g_h;

    int b1 = g_off1[n], e1 = g_off1[n + 1];
    float4 s1 = gather_dir3(g_nbr1, hv, b1, e1, half, l16);
    float inv1 = 1.0f / (float)max(e1 - b1, 1);

    int b2 = g_off2[n], e2 = g_off2[n + 1];
    float4 s2 = gather_dir3(g_nbr2, hv, b2, e2, half, l16);
    float inv2 = 1.0f / (float)max(e2 - b2, 1);

    s1.x += __shfl_xor_sync(0xffffffffu, s1.x, 16);
    s1.y += __shfl_xor_sync(0xffffffffu, s1.y, 16);
    s1.z += __shfl_xor_sync(0xffffffffu, s1.z, 16);
    s1.w += __shfl_xor_sync(0xffffffffu, s1.w, 16);
    s2.x += __shfl_xor_sync(0xffffffffu, s2.x, 16);
    s2.y += __shfl_xor_sync(0xffffffffu, s2.y, 16);
    s2.z += __shfl_xor_sync(0xffffffffu, s2.z, 16);
    s2.w += __shfl_xor_sync(0xffffffffu, s2.w, 16);

    if (half == 0) {
        ((float4*)g_s1)[n * 16 + l16] =
            make_float4(s1.x * inv1, s1.y * inv1, s1.z * inv1, s1.w * inv1);
        ((float4*)g_s2)[n * 16 + l16] =
            make_float4(s2.x * inv2, s2.y * inv2, s2.z * inv2, s2.w * inv2);
    }
}

// ===== GEMM v6.2 + probe flag: f32x2 node-pair packing, LT=2 =================
#define LT   2
#define TILE 64
#define KL   192
#define XPL  194                     // x row stride (ull), even for ST.128
#define LAYER_SMEM (KL * 68 * (int)sizeof(float) + (TILE/2) * XPL * (int)sizeof(ull))

__global__ void __launch_bounds__(256) k_layer(
        const float* __restrict__ w1, const float* __restrict__ w2,
        const float* __restrict__ wr, const float* __restrict__ rb,
        int l, int probe) {
    extern __shared__ float sm[];
    float* sw  = sm;                           // [192][68]
    ull*   sxu = (ull*)(sm + KL * 68);         // [32 pairs][194]
    const int tid = threadIdx.x;
    float* __restrict__ hout = probe ? g_dump : g_h;

    for (int s = 0; s < 3; s++) {
        const float* w = (s == 0) ? wr : (s == 1) ? w1 : w2;
        for (int i4 = tid; i4 < 64 * 16; i4 += 256) {
            int c = i4 >> 4, kq = i4 & 15;
            float4 wv = ((const float4*)w)[c * 16 + kq];
            float* dst = sw + (s * 64 + 4 * kq) * 68 + c;
            dst[0]      = wv.x;
            dst[68]     = wv.y;
            dst[2 * 68] = wv.z;
            dst[3 * 68] = wv.w;
        }
    }
    const int pg = tid >> 4;                   // 0..15
    const int cq = tid & 15;
    const float4 bv = ((const float4*)rb)[cq];
    const ull bi0 = pack2(bv.x, bv.x), bi1 = pack2(bv.y, bv.y);
    const ull bi2 = pack2(bv.z, bv.z), bi3 = pack2(bv.w, bv.w);
    const float4* sw4 = (const float4*)sw;     // stride 17

    for (int t = 0; t < LT; t++) {
        int node0 = (blockIdx.x * LT + t) * TILE;
        __syncthreads();
        for (int i = tid; i < (TILE / 2) * (KL / 4); i += 256) {
            int p = i / 48, kq = i % 48;
            int src = kq >> 4, k4 = kq & 15;
            int na = node0 + 2 * p;     if (na >= NN) na = NN - 1;
            int nb = na + 1;            if (nb >= NN) nb = NN - 1;
            const float* base = (src == 0) ? g_h : (src == 1) ? g_s1 : g_s2;
            float4 va = ((const float4*)(base + na * D))[k4];
            float4 vb = ((const float4*)(base + nb * D))[k4];
            ulonglong2* dst = (ulonglong2*)(sxu + p * XPL + 4 * kq);
            dst[0] = make_ulonglong2(pack2(va.x, vb.x), pack2(va.y, vb.y));
            dst[1] = make_ulonglong2(pack2(va.z, vb.z), pack2(va.w, vb.w));
        }
        __syncthreads();

        ull a0 = bi0, a1 = bi1, a2 = bi2, a3 = bi3;    // node pair 2pg
        ull b0 = bi0, b1 = bi1, b2 = bi2, b3 = bi3;    // node pair 2pg+1
        const ull* x0r = sxu + (2 * pg) * XPL;
        const ull* x1r = sxu + (2 * pg + 1) * XPL;
#pragma unroll 4
        for (int k = 0; k < KL; k++) {
            float4 w4 = sw4[k * 17 + cq];
            ull w0 = pack2(w4.x, w4.x), wq1 = pack2(w4.y, w4.y);
            ull w2 = pack2(w4.z, w4.z), w3 = pack2(w4.w, w4.w);
            ull x0 = x0r[k], x1 = x1r[k];
            ffma2(a0, x0, w0); ffma2(a1, x0, wq1);
            ffma2(a2, x0, w2); ffma2(a3, x0, w3);
            ffma2(b0, x1, w0); ffma2(b1, x1, wq1);
            ffma2(b2, x1, w2); ffma2(b3, x1, w3);
        }
        float2 p0 = unpack2(a0), p1 = unpack2(a1), p2 = unpack2(a2), p3 = unpack2(a3);
        float2 q0 = unpack2(b0), q1 = unpack2(b1), q2 = unpack2(b2), q3 = unpack2(b3);
        int nb0 = node0 + 4 * pg;
        int cb = (l + 1) * D;
#define EMIT(N, RX, RY, RZ, RW) \
        if ((N) < NN) { \
            float4 r = make_float4(fmaxf(RX, 0.f), fmaxf(RY, 0.f), \
                                   fmaxf(RZ, 0.f), fmaxf(RW, 0.f)); \
            ((float4*)(hout + (N) * D))[cq] = r; \
            ((float4*)(g_cat + (N) * DCAT + cb))[cq] = r; \
        }
        EMIT(nb0 + 0, p0.x, p1.x, p2.x, p3.x)
        EMIT(nb0 + 1, p0.y, p1.y, p2.y, p3.y)
        EMIT(nb0 + 2, q0.x, q1.x, q2.x, q3.x)
        EMIT(nb0 + 3, q0.y, q1.y, q2.y, q3.y)
#undef EMIT
    }
}

// ===== final GEMM v6.2 (unchanged) ===========================================
#define KF  256
#define XPF 258                      // even for ST.128
#define FINAL_SMEM (KF * 68 * (int)sizeof(float) + (TILE/2) * XPF * (int)sizeof(ull))

__global__ void __launch_bounds__(256) k_final(
        const float* __restrict__ fw, const float* __restrict__ fb,
        float* __restrict__ out) {
    extern __shared__ float sm[];
    float* sw  = sm;                           // [256][68]
    ull*   sxu = (ull*)(sm + KF * 68);         // [32][258]
    const int tid = threadIdx.x;

    for (int i4 = tid; i4 < 64 * 64; i4 += 256) {
        int c = i4 >> 6, kq = i4 & 63;
        float4 wv = ((const float4*)fw)[c * 64 + kq];
        float* dst = sw + (4 * kq) * 68 + c;
        dst[0]      = wv.x;
        dst[68]     = wv.y;
        dst[2 * 68] = wv.z;
        dst[3 * 68] = wv.w;
    }
    const int pg = tid >> 4;
    const int cq = tid & 15;
    const float4 bv = ((const float4*)fb)[cq];
    const ull bi0 = pack2(bv.x, bv.x), bi1 = pack2(bv.y, bv.y);
    const ull bi2 = pack2(bv.z, bv.z), bi3 = pack2(bv.w, bv.w);
    const float4* sw4 = (const float4*)sw;

    for (int t = 0; t < LT; t++) {
        int node0 = (blockIdx.x * LT + t) * TILE;
        __syncthreads();
        for (int i = tid; i < (TILE / 2) * (KF / 4); i += 256) {
            int p = i >> 6, kq = i & 63;
            int na = node0 + 2 * p;     if (na >= NN) na = NN - 1;
            int nb = na + 1;            if (nb >= NN) nb = NN - 1;
            float4 va = ((const float4*)(g_cat + na * DCAT))[kq];
            float4 vb = ((const float4*)(g_cat + nb * DCAT))[kq];
            ulonglong2* dst = (ulonglong2*)(sxu + p * XPF + 4 * kq);
            dst[0] = make_ulonglong2(pack2(va.x, vb.x), pack2(va.y, vb.y));
            dst[1] = make_ulonglong2(pack2(va.z, vb.z), pack2(va.w, vb.w));
        }
        __syncthreads();

        ull a0 = bi0, a1 = bi1, a2 = bi2, a3 = bi3;
        ull b0 = bi0, b1 = bi1, b2 = bi2, b3 = bi3;
        const ull* x0r = sxu + (2 * pg) * XPF;
        const ull* x1r = sxu + (2 * pg + 1) * XPF;
#pragma unroll 4
        for (int k = 0; k < KF; k++) {
            float4 w4 = sw4[k * 17 + cq];
            ull w0 = pack2(w4.x, w4.x), wq1 = pack2(w4.y, w4.y);
            ull w2 = pack2(w4.z, w4.z), w3 = pack2(w4.w, w4.w);
            ull x0 = x0r[k], x1 = x1r[k];
            ffma2(a0, x0, w0); ffma2(a1, x0, wq1);
            ffma2(a2, x0, w2); ffma2(a3, x0, w3);
            ffma2(b0, x1, w0); ffma2(b1, x1, wq1);
            ffma2(b2, x1, w2); ffma2(b3, x1, w3);
        }
        float2 p0 = unpack2(a0), p1 = unpack2(a1), p2 = unpack2(a2), p3 = unpack2(a3);
        float2 q0 = unpack2(b0), q1 = unpack2(b1), q2 = unpack2(b2), q3 = unpack2(b3);
        int nb0 = node0 + 4 * pg;
        if (nb0 + 0 < NN) ((float4*)(out + (nb0 + 0) * D))[cq] =
            make_float4(p0.x, p1.x, p2.x, p3.x);
        if (nb0 + 1 < NN) ((float4*)(out + (nb0 + 1) * D))[cq] =
            make_float4(p0.y, p1.y, p2.y, p3.y);
        if (nb0 + 2 < NN) ((float4*)(out + (nb0 + 2) * D))[cq] =
            make_float4(q0.x, q1.x, q2.x, q3.x);
        if (nb0 + 3 < NN) ((float4*)(out + (nb0 + 3) * D))[cq] =
            make_float4(q0.y, q1.y, q2.y, q3.y);
    }
}

// ---------------- launch -----------------------------------------------------
extern "C" void kernel_launch(void* const* d_in, const int* in_sizes, int n_in,
                              void* d_out, int out_size) {
    const float* x     = (const float*)d_in[0];
    const int*   ei    = (const int*)d_in[1];
    const float* lin1  = (const float*)d_in[2];
    const float* lin2  = (const float*)d_in[3];
    const float* rootw = (const float*)d_in[4];
    const float* rootb = (const float*)d_in[5];
    const float* fw    = (const float*)d_in[6];
    const float* fb    = (const float*)d_in[7];
    float*       out   = (float*)d_out;

    cudaFuncSetAttribute(k_layer, cudaFuncAttributeMaxDynamicSharedMemorySize, LAYER_SMEM);
    cudaFuncSetAttribute(k_final, cudaFuncAttributeMaxDynamicSharedMemorySize, FINAL_SMEM);

    k_init<<<(NN * D + 255) / 256, 256>>>(x, ei);
    k_scan<<<1, 1024>>>();
    k_fill<<<(NE + 255) / 256, 256>>>(ei);

    const int agg_grid  = (NN * 32 + 255) / 256;
    const int gemm_grid = (NN + LT * TILE - 1) / (LT * TILE);   // 391

    // PROBE: identical k_layer as the 4th launch so ncu's fixed capture slot
    // lands on the GEMM. Writes h-output to g_dump (never read); its g_cat
    // slice is overwritten by the real layer-0 pass below.
    k_layer<<<gemm_grid, 256, LAYER_SMEM>>>(lin1, lin2, rootw, rootb, 0, 1);

    for (int l = 0; l < NL; l++) {
        k_agg  <<<agg_grid, 256>>>();
        k_layer<<<gemm_grid, 256, LAYER_SMEM>>>(lin1 + l * D * D, lin2 + l * D * D,
                                                rootw + l * D * D, rootb + l * D, l, 0);
    }
    k_final<<<gemm_grid, 256, FINAL_SMEM>>>(fw, fb, out);
}

// round 15
// speedup vs baseline: 1.0842x; 1.0842x over previous
#include <cuda_runtime.h>

#define NN 50000
#define NE 800000
#define D  64
#define NL 3
#define DCAT (D + NL * D)   // 256

typedef unsigned long long ull;

// ---------------- scratch (device globals; zero-initialized at load) --------
__device__ int   g_cnt1[NN], g_cnt2[NN], g_cur1[NN], g_cur2[NN];
__device__ int   g_off1[NN + 1], g_off2[NN + 1];
__device__ int   g_nbr1[NE], g_nbr2[NE];
__device__ __align__(16) float g_h[NN * D];
__device__ __align__(16) float g_s1[NN * D];
__device__ __align__(16) float g_s2[NN * D];
__device__ __align__(16) float g_cat[NN * DCAT];

__device__ __forceinline__ int clampi(int v) {
    return v < 0 ? 0 : (v >= NN ? NN - 1 : v);
}

// ---------------- packed f32x2 helpers ---------------------------------------
__device__ __forceinline__ void ffma2(ull& a, ull x, ull w) {
    asm("fma.rn.f32x2 %0, %1, %2, %0;" : "+l"(a) : "l"(x), "l"(w));
}
__device__ __forceinline__ float2 unpack2(ull v) {
    float2 r; asm("mov.b64 {%0,%1}, %2;" : "=f"(r.x), "=f"(r.y) : "l"(v)); return r;
}
__device__ __forceinline__ ull pack2(float x, float y) {
    ull r; asm("mov.b64 %0, {%1,%2};" : "=l"(r) : "f"(x), "f"(y)); return r;
}

// ---- init + edge histogram (cnt zeroed by previous call's k_fill) ----------
__global__ void k_init(const float* __restrict__ x, const int* __restrict__ ei) {
    int i = blockIdx.x * blockDim.x + threadIdx.x;
    if (i < NN * D) {
        float v = x[i];
        g_h[i] = v;
        g_cat[(i >> 6) * DCAT + (i & 63)] = v;
    }
    if (i < NE) {
        atomicAdd(&g_cnt1[clampi(ei[NE + i])], 1);
        atomicAdd(&g_cnt2[clampi(ei[i])], 1);
    }
}

// ---- exclusive scan (also re-zeroes g_cur) ----------------------------------
__global__ void k_scan() {
    __shared__ int ssum1[1024], ssum2[1024];
    const int t  = threadIdx.x;
    for (int i = t; i < NN; i += 1024) { g_cur1[i] = 0; g_cur2[i] = 0; }

    const int CH = (NN + 1023) / 1024;
    const int base = t * CH;
    int s1 = 0, s2 = 0;
    for (int i = 0; i < CH; i++) {
        int n = base + i;
        if (n < NN) { s1 += g_cnt1[n]; s2 += g_cnt2[n]; }
    }
    ssum1[t] = s1; ssum2[t] = s2;
    __syncthreads();

    for (int off = 1; off < 1024; off <<= 1) {
        int a1 = ssum1[t], a2 = ssum2[t];
        int b1 = (t >= off) ? ssum1[t - off] : 0;
        int b2 = (t >= off) ? ssum2[t - off] : 0;
        __syncthreads();
        ssum1[t] = a1 + b1; ssum2[t] = a2 + b2;
        __syncthreads();
    }

    int ex1 = (t == 0) ? 0 : ssum1[t - 1];
    int ex2 = (t == 0) ? 0 : ssum2[t - 1];
    for (int i = 0; i < CH; i++) {
        int n = base + i;
        if (n < NN) {
            g_off1[n] = ex1; ex1 += g_cnt1[n];
            g_off2[n] = ex2; ex2 += g_cnt2[n];
        }
    }
    if (t == 0) {
        g_off1[NN] = ssum1[1023];
        g_off2[NN] = ssum2[1023];
    }
}

// ---- fill edge lists (also re-zeroes g_cnt for next call) -------------------
__global__ void k_fill(const int* __restrict__ ei) {
    int e = blockIdx.x * blockDim.x + threadIdx.x;
    if (e >= NE) return;
    if (e < NN) { g_cnt1[e] = 0; g_cnt2[e] = 0; }
    int s = clampi(ei[e]);
    int d = clampi(ei[NE + e]);
    g_nbr1[g_off1[d] + atomicAdd(&g_cur1[d], 1)] = s;
    g_nbr2[g_off2[s] + atomicAdd(&g_cur2[s], 1)] = d;
}

// ======= agg v5 fused (R12 measured-best, 39.4us) ============================
__device__ __forceinline__ float4 gather_dir3(const int* __restrict__ nbr,
                                              const float4* __restrict__ hv,
                                              int b, int e, int half, int l16) {
    float4 a0 = make_float4(0.f, 0.f, 0.f, 0.f);
    float4 a1 = make_float4(0.f, 0.f, 0.f, 0.f);
    int j = b;
    for (; j + 8 <= e; j += 8) {                 // 8 nbrs: 4 idx + 4 LDG.128
        int i0 = __ldg(nbr + j     + half);
        int i1 = __ldg(nbr + j + 2 + half);
        int i2 = __ldg(nbr + j + 4 + half);
        int i3 = __ldg(nbr + j + 6 + half);
        float4 v0 = hv[i0 * 16 + l16];
        float4 v1 = hv[i1 * 16 + l16];
        float4 v2 = hv[i2 * 16 + l16];
        float4 v3 = hv[i3 * 16 + l16];
        a0.x += v0.x + v1.x; a0.y += v0.y + v1.y;
        a0.z += v0.z + v1.z; a0.w += v0.w + v1.w;
        a1.x += v2.x + v3.x; a1.y += v2.y + v3.y;
        a1.z += v2.z + v3.z; a1.w += v2.w + v3.w;
    }
    for (; j < e; j += 2) {
        int jj = j + half;
        if (jj < e) {
            int i0 = __ldg(nbr + jj);
            float4 v0 = hv[i0 * 16 + l16];
            a0.x += v0.x; a0.y += v0.y; a0.z += v0.z; a0.w += v0.w;
        }
    }
    a0.x += a1.x; a0.y += a1.y; a0.z += a1.z; a0.w += a1.w;
    return a0;
}

__global__ void k_agg() {
    int gw   = (blockIdx.x * blockDim.x + threadIdx.x) >> 5;
    int lane = threadIdx.x & 31;
    if (gw >= NN) return;
    const int n    = gw;
    const int half = lane >> 4;
    const int l16  = lane & 15;
    const float4* __restrict__ hv = (const float4*)g_h;

    int b1 = g_off1[n], e1 = g_off1[n + 1];
    float4 s1 = gather_dir3(g_nbr1, hv, b1, e1, half, l16);
    float inv1 = 1.0f / (float)max(e1 - b1, 1);

    int b2 = g_off2[n], e2 = g_off2[n + 1];
    float4 s2 = gather_dir3(g_nbr2, hv, b2, e2, half, l16);
    float inv2 = 1.0f / (float)max(e2 - b2, 1);

    s1.x += __shfl_xor_sync(0xffffffffu, s1.x, 16);
    s1.y += __shfl_xor_sync(0xffffffffu, s1.y, 16);
    s1.z += __shfl_xor_sync(0xffffffffu, s1.z, 16);
    s1.w += __shfl_xor_sync(0xffffffffu, s1.w, 16);
    s2.x += __shfl_xor_sync(0xffffffffu, s2.x, 16);
    s2.y += __shfl_xor_sync(0xffffffffu, s2.y, 16);
    s2.z += __shfl_xor_sync(0xffffffffu, s2.z, 16);
    s2.w += __shfl_xor_sync(0xffffffffu, s2.w, 16);

    if (half == 0) {
        ((float4*)g_s1)[n * 16 + l16] =
            make_float4(s1.x * inv1, s1.y * inv1, s1.z * inv1, s1.w * inv1);
        ((float4*)g_s2)[n * 16 + l16] =
            make_float4(s2.x * inv2, s2.y * inv2, s2.z * inv2, s2.w * inv2);
    }
}

// ===== GEMM v6.3: f32x2 node-pair packing, 2-k batched loads =================
#define LT   2
#define TILE 64
#define KL   192
#define XPL  194                     // x row stride (ull), even for LDS/ST.128
#define LAYER_SMEM (KL * 68 * (int)sizeof(float) + (TILE/2) * XPL * (int)sizeof(ull))

// 16 FFMA2 on two k's; loads for both k's batched by the caller.
#define K2STEP(wA, wB, xA, xB)                                         \
    {                                                                  \
        ull w0 = pack2(wA.x, wA.x), w1_ = pack2(wA.y, wA.y);           \
        ull w2_ = pack2(wA.z, wA.z), w3_ = pack2(wA.w, wA.w);          \
        ffma2(a0, xA.x, w0);  ffma2(a1, xA.x, w1_);                    \
        ffma2(a2, xA.x, w2_); ffma2(a3, xA.x, w3_);                    \
        ffma2(b0, xB.x, w0);  ffma2(b1, xB.x, w1_);                    \
        ffma2(b2, xB.x, w2_); ffma2(b3, xB.x, w3_);                    \
        w0 = pack2(wB.x, wB.x);  w1_ = pack2(wB.y, wB.y);              \
        w2_ = pack2(wB.z, wB.z); w3_ = pack2(wB.w, wB.w);              \
        ffma2(a0, xA.y, w0);  ffma2(a1, xA.y, w1_);                    \
        ffma2(a2, xA.y, w2_); ffma2(a3, xA.y, w3_);                    \
        ffma2(b0, xB.y, w0);  ffma2(b1, xB.y, w1_);                    \
        ffma2(b2, xB.y, w2_); ffma2(b3, xB.y, w3_);                    \
    }

__global__ void __launch_bounds__(256) k_layer(
        const float* __restrict__ w1, const float* __restrict__ w2,
        const float* __restrict__ wr, const float* __restrict__ rb, int l) {
    extern __shared__ float sm[];
    float* sw  = sm;                           // [192][68]
    ull*   sxu = (ull*)(sm + KL * 68);         // [32 pairs][194]
    const int tid = threadIdx.x;

    for (int s = 0; s < 3; s++) {
        const float* w = (s == 0) ? wr : (s == 1) ? w1 : w2;
        for (int i4 = tid; i4 < 64 * 16; i4 += 256) {
            int c = i4 >> 4, kq = i4 & 15;
            float4 wv = ((const float4*)w)[c * 16 + kq];
            float* dst = sw + (s * 64 + 4 * kq) * 68 + c;
            dst[0]      = wv.x;
            dst[68]     = wv.y;
            dst[2 * 68] = wv.z;
            dst[3 * 68] = wv.w;
        }
    }
    const int pg = tid >> 4;                   // 0..15
    const int cq = tid & 15;
    const float4 bv = ((const float4*)rb)[cq];
    const ull bi0 = pack2(bv.x, bv.x), bi1 = pack2(bv.y, bv.y);
    const ull bi2 = pack2(bv.z, bv.z), bi3 = pack2(bv.w, bv.w);
    const float4* sw4 = (const float4*)sw;     // stride 17

    for (int t = 0; t < LT; t++) {
        int node0 = (blockIdx.x * LT + t) * TILE;
        __syncthreads();
        for (int i = tid; i < (TILE / 2) * (KL / 4); i += 256) {
            int p = i / 48, kq = i % 48;
            int src = kq >> 4, k4 = kq & 15;
            int na = node0 + 2 * p;     if (na >= NN) na = NN - 1;
            int nb = na + 1;            if (nb >= NN) nb = NN - 1;
            const float* base = (src == 0) ? g_h : (src == 1) ? g_s1 : g_s2;
            float4 va = ((const float4*)(base + na * D))[k4];
            float4 vb = ((const float4*)(base + nb * D))[k4];
            ulonglong2* dst = (ulonglong2*)(sxu + p * XPL + 4 * kq);
            dst[0] = make_ulonglong2(pack2(va.x, vb.x), pack2(va.y, vb.y));
            dst[1] = make_ulonglong2(pack2(va.z, vb.z), pack2(va.w, vb.w));
        }
        __syncthreads();

        ull a0 = bi0, a1 = bi1, a2 = bi2, a3 = bi3;    // node pair 2pg
        ull b0 = bi0, b1 = bi1, b2 = bi2, b3 = bi3;    // node pair 2pg+1
        const ull* x0r = sxu + (2 * pg) * XPL;
        const ull* x1r = sxu + (2 * pg + 1) * XPL;
#pragma unroll 4
        for (int k = 0; k < KL; k += 2) {
            float4 wA = sw4[k * 17 + cq];
            float4 wB = sw4[(k + 1) * 17 + cq];
            ulonglong2 xA = *(const ulonglong2*)(x0r + k);
            ulonglong2 xB = *(const ulonglong2*)(x1r + k);
            K2STEP(wA, wB, xA, xB)
        }
        float2 p0 = unpack2(a0), p1 = unpack2(a1), p2 = unpack2(a2), p3 = unpack2(a3);
        float2 q0 = unpack2(b0), q1 = unpack2(b1), q2 = unpack2(b2), q3 = unpack2(b3);
        int nb0 = node0 + 4 * pg;
        int cb = (l + 1) * D;
#define EMIT(N, RX, RY, RZ, RW) \
        if ((N) < NN) { \
            float4 r = make_float4(fmaxf(RX, 0.f), fmaxf(RY, 0.f), \
                                   fmaxf(RZ, 0.f), fmaxf(RW, 0.f)); \
            ((float4*)(g_h + (N) * D))[cq] = r; \
            ((float4*)(g_cat + (N) * DCAT + cb))[cq] = r; \
        }
        EMIT(nb0 + 0, p0.x, p1.x, p2.x, p3.x)
        EMIT(nb0 + 1, p0.y, p1.y, p2.y, p3.y)
        EMIT(nb0 + 2, q0.x, q1.x, q2.x, q3.x)
        EMIT(nb0 + 3, q0.y, q1.y, q2.y, q3.y)
#undef EMIT
    }
}

// ===== final GEMM v6.3 =======================================================
#define KF  256
#define XPF 258                      // even for LDS/ST.128
#define FINAL_SMEM (KF * 68 * (int)sizeof(float) + (TILE/2) * XPF * (int)sizeof(ull))

__global__ void __launch_bounds__(256) k_final(
        const float* __restrict__ fw, const float* __restrict__ fb,
        float* __restrict__ out) {
    extern __shared__ float sm[];
    float* sw  = sm;                           // [256][68]
    ull*   sxu = (ull*)(sm + KF * 68);         // [32][258]
    const int tid = threadIdx.x;

    for (int i4 = tid; i4 < 64 * 64; i4 += 256) {
        int c = i4 >> 6, kq = i4 & 63;
        float4 wv = ((const float4*)fw)[c * 64 + kq];
        float* dst = sw + (4 * kq) * 68 + c;
        dst[0]      = wv.x;
        dst[68]     = wv.y;
        dst[2 * 68] = wv.z;
        dst[3 * 68] = wv.w;
    }
    const int pg = tid >> 4;
    const int cq = tid & 15;
    const float4 bv = ((const float4*)fb)[cq];
    const ull bi0 = pack2(bv.x, bv.x), bi1 = pack2(bv.y, bv.y);
    const ull bi2 = pack2(bv.z, bv.z), bi3 = pack2(bv.w, bv.w);
    const float4* sw4 = (const float4*)sw;

    for (int t = 0; t < LT; t++) {
        int node0 = (blockIdx.x * LT + t) * TILE;
        __syncthreads();
        for (int i = tid; i < (TILE / 2) * (KF / 4); i += 256) {
            int p = i >> 6, kq = i & 63;
            int na = node0 + 2 * p;     if (na >= NN) na = NN - 1;
            int nb = na + 1;            if (nb >= NN) nb = NN - 1;
            float4 va = ((const float4*)(g_cat + na * DCAT))[kq];
            float4 vb = ((const float4*)(g_cat + nb * DCAT))[kq];
            ulonglong2* dst = (ulonglong2*)(sxu + p * XPF + 4 * kq);
            dst[0] = make_ulonglong2(pack2(va.x, vb.x), pack2(va.y, vb.y));
            dst[1] = make_ulonglong2(pack2(va.z, vb.z), pack2(va.w, vb.w));
        }
        __syncthreads();

        ull a0 = bi0, a1 = bi1, a2 = bi2, a3 = bi3;
        ull b0 = bi0, b1 = bi1, b2 = bi2, b3 = bi3;
        const ull* x0r = sxu + (2 * pg) * XPF;
        const ull* x1r = sxu + (2 * pg + 1) * XPF;
#pragma unroll 4
        for (int k = 0; k < KF; k += 2) {
            float4 wA = sw4[k * 17 + cq];
            float4 wB = sw4[(k + 1) * 17 + cq];
            ulonglong2 xA = *(const ulonglong2*)(x0r + k);
            ulonglong2 xB = *(const ulonglong2*)(x1r + k);
            K2STEP(wA, wB, xA, xB)
        }
        float2 p0 = unpack2(a0), p1 = unpack2(a1), p2 = unpack2(a2), p3 = unpack2(a3);
        float2 q0 = unpack2(b0), q1 = unpack2(b1), q2 = unpack2(b2), q3 = unpack2(b3);
        int nb0 = node0 + 4 * pg;
        if (nb0 + 0 < NN) ((float4*)(out + (nb0 + 0) * D))[cq] =
            make_float4(p0.x, p1.x, p2.x, p3.x);
        if (nb0 + 1 < NN) ((float4*)(out + (nb0 + 1) * D))[cq] =
            make_float4(p0.y, p1.y, p2.y, p3.y);
        if (nb0 + 2 < NN) ((float4*)(out + (nb0 + 2) * D))[cq] =
            make_float4(q0.x, q1.x, q2.x, q3.x);
        if (nb0 + 3 < NN) ((float4*)(out + (nb0 + 3) * D))[cq] =
            make_float4(q0.y, q1.y, q2.y, q3.y);
    }
}

// ---------------- launch -----------------------------------------------------
extern "C" void kernel_launch(void* const* d_in, const int* in_sizes, int n_in,
                              void* d_out, int out_size) {
    const float* x     = (const float*)d_in[0];
    const int*   ei    = (const int*)d_in[1];
    const float* lin1  = (const float*)d_in[2];
    const float* lin2  = (const float*)d_in[3];
    const float* rootw = (const float*)d_in[4];
    const float* rootb = (const float*)d_in[5];
    const float* fw    = (const float*)d_in[6];
    const float* fb    = (const float*)d_in[7];
    float*       out   = (float*)d_out;

    cudaFuncSetAttribute(k_layer, cudaFuncAttributeMaxDynamicSharedMemorySize, LAYER_SMEM);
    cudaFuncSetAttribute(k_final, cudaFuncAttributeMaxDynamicSharedMemorySize, FINAL_SMEM);

    k_init<<<(NN * D + 255) / 256, 256>>>(x, ei);
    k_scan<<<1, 1024>>>();
    k_fill<<<(NE + 255) / 256, 256>>>(ei);

    const int agg_grid  = (NN * 32 + 255) / 256;
    const int gemm_grid = (NN + LT * TILE - 1) / (LT * TILE);   // 391

    for (int l = 0; l < NL; l++) {
        k_agg  <<<agg_grid, 256>>>();
        k_layer<<<gemm_grid, 256, LAYER_SMEM>>>(lin1 + l * D * D, lin2 + l * D * D,
                                                rootw + l * D * D, rootb + l * D, l);
    }
    k_final<<<gemm_grid, 256, FINAL_SMEM>>>(fw, fb, out);
}